// round 17
// baseline (speedup 1.0000x reference)
#include <cuda_runtime.h>
#include <cuda_fp16.h>
#include <cstdint>

#define WSIZE 9216
#define PSTRIDE 9248

#define XPITCH 20                        // words/pixel: 16 data + 4 pad (conflict-free, proven R5)
#define XROWW  (130 * XPITCH)            // 2600
#define XT_WORDS (6 * XROWW)             // 15600
#define WPITCH 148                       // words/filter: 144 data + 4 pad (proven R5)
#define WT_WORDS (32 * WPITCH)           // 4736
#define SMEM_BYTES ((XT_WORDS + WT_WORDS) * 4)   // 81344 -> 2 CTAs/SM

// precomputed W^T fp16, plain k-major: [b][f][WPITCH words], word w = (k=2w,2w+1)
__device__ uint32_t gWT[32 * WT_WORDS];

__device__ __forceinline__ uint32_t pack2(float a, float b) {
    __half2 h = __floats2half2_rn(a, b);
    return *(uint32_t*)&h;
}
__device__ __forceinline__ void mma_f16(float& c0, float& c1, float& c2, float& c3,
                                        uint32_t a0, uint32_t a1, uint32_t a2, uint32_t a3,
                                        uint32_t b0, uint32_t b1) {
    asm volatile(
        "mma.sync.aligned.m16n8k16.row.col.f32.f16.f16.f32 "
        "{%0,%1,%2,%3}, {%4,%5,%6,%7}, {%8,%9}, {%0,%1,%2,%3};"
        : "+f"(c0), "+f"(c1), "+f"(c2), "+f"(c3)
        : "r"(a0), "r"(a1), "r"(a2), "r"(a3), "r"(b0), "r"(b1));
}

// ---- precompute W^T fp16 (plain k-major), 9 small blocks per batch ----
__global__ __launch_bounds__(256)
void wprep(const float* __restrict__ params) {
    __shared__ float s[32 * 33];
    const int b  = blockIdx.x / 9;
    const int kc = blockIdx.x % 9;
    const int tid = threadIdx.x;
    const float* pw = params + (long)b * PSTRIDE + kc * 1024;
    #pragma unroll
    for (int i = tid; i < 1024; i += 256) {
        int k = i >> 5, f = i & 31;
        s[k * 33 + f] = pw[i];
    }
    __syncthreads();
    uint32_t* gw = gWT + b * WT_WORDS + kc * 16;
    #pragma unroll
    for (int i = tid; i < 512; i += 256) {
        int f = i >> 4, n = i & 15;
        gw[f * WPITCH + n] = pack2(s[(2 * n) * 33 + f], s[(2 * n + 1) * 33 + f]);
    }
}

__global__ __launch_bounds__(256, 2)
void conv_mma_f16(const float* __restrict__ x, const float* __restrict__ params,
                  float* __restrict__ out) {
    asm volatile("griddepcontrol.wait;" ::: "memory");

    extern __shared__ uint32_t smem[];
    uint32_t* sX = smem;                 // [row 0..5][pix 0..129][XPITCH], fp16 k-major
    uint32_t* sW = smem + XT_WORDS;      // [f][WPITCH], fp16 k-major

    const int tid = threadIdx.x;
    const int wid = tid >> 5;
    const int lid = tid & 31;
    const int g   = lid >> 2;
    const int t   = lid & 3;
    const int y0  = blockIdx.x * 4;      // 4 output rows per CTA
    const int b   = blockIdx.y;

    // ---- copy precomputed W^T (uint4 memcpy) ----
    const uint4* gw4 = (const uint4*)(gWT + b * WT_WORDS);
    #pragma unroll
    for (int it = 0; it < 5; it++) {
        int idx = tid + it * 256;
        if (idx < WT_WORDS / 4) ((uint4*)sW)[idx] = gw4[idx];
    }

    // ---- build X tile: input rows y0-1 .. y0+4, pixels -1..128 at 0..129 ----
    const float* xb = x + (long)b * (128 * 128 * 32);
    #pragma unroll
    for (int it = 0; it < 24; it++) {
        int idx = tid + it * 256;        // 0..6143
        int c4  = idx & 7;
        int px  = (idx >> 3) & 127;
        int row = idx >> 10;             // 0..5
        int gy  = y0 + row - 1;
        uint2 v = make_uint2(0u, 0u);
        if ((unsigned)gy < 128u) {
            float4 s = *(const float4*)(xb + ((gy * 128 + px) * 32 + c4 * 4));
            v.x = pack2(s.x, s.y);
            v.y = pack2(s.z, s.w);
        }
        *(uint2*)(sX + row * XROWW + (px + 1) * XPITCH + c4 * 2) = v;
    }
    if (tid < 192) {
        int row = tid >> 5, rem = tid & 31;
        int pix = (rem >> 4) ? 129 : 0;
        sX[row * XROWW + pix * XPITCH + (rem & 15)] = 0u;
    }
    __syncthreads();

    const int yl = wid >> 1;             // local output row 0..3
    const int m0 = (wid & 1) * 64;       // 64 px per warp
    const bool hi = (lid >= 28);         // g == 7

    float acc[4][4][4];
    #pragma unroll
    for (int mi = 0; mi < 4; mi++)
        #pragma unroll
        for (int nt = 0; nt < 4; nt++)
            #pragma unroll
            for (int j = 0; j < 4; j++) acc[mi][nt][j] = 0.f;

    #pragma unroll
    for (int kh = 0; kh < 3; kh++) {
        const uint32_t* xr = sX + (yl + kh) * XROWW;
        #pragma unroll
        for (int c16 = 0; c16 < 2; c16++) {
            // ---- load A fragments once (kw = 0) ----
            uint32_t A0[4], A1[4], A2[4], A3[4];
            #pragma unroll
            for (int mi = 0; mi < 4; mi++) {
                const uint32_t* ap = xr + (m0 + mi * 16 + g) * XPITCH + c16 * 8 + t;
                A0[mi] = ap[0];
                A1[mi] = ap[8 * XPITCH];
                A2[mi] = ap[4];
                A3[mi] = ap[8 * XPITCH + 4];
            }

            #pragma unroll
            for (int kw = 0; kw < 3; kw++) {
                const int k0w = kh * 48 + kw * 16 + c16 * 8;

                // B fragments (scalar LDS, proven conflict-free)
                uint32_t b0[4], b1[4];
                const uint32_t* wp = sW + k0w + t;
                #pragma unroll
                for (int nt = 0; nt < 4; nt++) {
                    int f = nt * 8 + g;
                    b0[nt] = wp[f * WPITCH];
                    b1[nt] = wp[f * WPITCH + 4];
                }

                #pragma unroll
                for (int mi = 0; mi < 4; mi++) {
                    #pragma unroll
                    for (int nt = 0; nt < 4; nt++)
                        mma_f16(acc[mi][nt][0], acc[mi][nt][1],
                                acc[mi][nt][2], acc[mi][nt][3],
                                A0[mi], A1[mi], A2[mi], A3[mi], b0[nt], b1[nt]);
                }

                // ---- shift A fragments one pixel (kw -> kw+1) via shuffles ----
                if (kw < 2) {
                    // mi=3 upper boundary rows come from smem (pixel m0+64+kw, broadcast)
                    const uint32_t* bnp = xr + (m0 + 64 + kw) * XPITCH + c16 * 8 + t;
                    uint32_t bnd1 = bnp[0];
                    uint32_t bnd3 = bnp[4];
                    #pragma unroll
                    for (int mi = 0; mi < 4; mi++) {
                        uint32_t n0 = __shfl_sync(0xFFFFFFFFu, A0[mi], lid + 4);
                        uint32_t c0 = __shfl_sync(0xFFFFFFFFu, A1[mi], t);
                        uint32_t n1 = __shfl_sync(0xFFFFFFFFu, A1[mi], lid + 4);
                        uint32_t c1 = (mi < 3) ? __shfl_sync(0xFFFFFFFFu, A0[mi + 1], t) : bnd1;
                        uint32_t n2 = __shfl_sync(0xFFFFFFFFu, A2[mi], lid + 4);
                        uint32_t c2 = __shfl_sync(0xFFFFFFFFu, A3[mi], t);
                        uint32_t n3 = __shfl_sync(0xFFFFFFFFu, A3[mi], lid + 4);
                        uint32_t c3 = (mi < 3) ? __shfl_sync(0xFFFFFFFFu, A2[mi + 1], t) : bnd3;
                        A0[mi] = hi ? c0 : n0;
                        A1[mi] = hi ? c1 : n1;
                        A2[mi] = hi ? c2 : n2;
                        A3[mi] = hi ? c3 : n3;
                    }
                }
            }
        }
    }

    // ---- epilogue: + bias, direct STG (R5-proven) ----
    const float* bp = params + (long)b * PSTRIDE + WSIZE;
    float* ob = out + ((long)(b * 128 + y0 + yl)) * 128 * 32;
    #pragma unroll
    for (int nt = 0; nt < 4; nt++) {
        int f = nt * 8 + t * 2;
        float2 bias = *(const float2*)(bp + f);
        #pragma unroll
        for (int mi = 0; mi < 4; mi++) {
            int px = m0 + mi * 16 + g;
            float2 o0, o1;
            o0.x = acc[mi][nt][0] + bias.x;
            o0.y = acc[mi][nt][1] + bias.y;
            o1.x = acc[mi][nt][2] + bias.x;
            o1.y = acc[mi][nt][3] + bias.y;
            *(float2*)(ob + px * 32 + f)       = o0;
            *(float2*)(ob + (px + 8) * 32 + f) = o1;
        }
    }
}

extern "C" void kernel_launch(void* const* d_in, const int* in_sizes, int n_in,
                              void* d_out, int out_size) {
    const float* x      = (const float*)d_in[0];
    const float* params = (const float*)d_in[1];
    float* out          = (float*)d_out;

    wprep<<<288, 256>>>(params);

    cudaFuncSetAttribute(conv_mma_f16, cudaFuncAttributeMaxDynamicSharedMemorySize, SMEM_BYTES);

    cudaLaunchConfig_t cfg = {};
    cfg.gridDim  = dim3(32, 32, 1);
    cfg.blockDim = dim3(256, 1, 1);
    cfg.dynamicSmemBytes = SMEM_BYTES;
    cudaLaunchAttribute attrs[1];
    attrs[0].id = cudaLaunchAttributeProgrammaticStreamSerialization;
    attrs[0].val.programmaticStreamSerializationAllowed = 1;
    cfg.attrs = attrs;
    cfg.numAttrs = 1;
    cudaLaunchKernelEx(&cfg, conv_mma_f16, x, params, out);
}